// round 14
// baseline (speedup 1.0000x reference)
#include <cuda_runtime.h>
#include <cuda_bf16.h>
#include <cstdint>

// Problem constants (fixed by the dataset)
#define NN 50000
#define EE 800000
#define IN_C 256
#define HID_C 128
#define OUT_C 64

// ---------------------------------------------------------------------------
// Scratch (device globals). All float4-accessed buffers 16B-aligned.
// g_deg relies on module-load zero-init; the fused kernel re-zeroes it each
// call (after its last reader), keeping the invariant across graph replays.
// ---------------------------------------------------------------------------
__device__ int   g_deg[NN];
__device__ float g_dinv[NN];
__device__ int   g_rowptr[NN + 1];
__device__ int   g_cursor[NN];
__device__ int   g_blocksums[64];
__device__ int   g_csr[EE];
__device__ __align__(16) float g_h1[(size_t)NN * HID_C];
__device__ __align__(16) float g_h2[(size_t)NN * OUT_C];
// Weight images: W^T in bf16 hi/lo, row-major [n][k] (k contiguous)
__device__ __align__(16) __nv_bfloat16 g_Wt1h[HID_C * IN_C];
__device__ __align__(16) __nv_bfloat16 g_Wt1l[HID_C * IN_C];
__device__ __align__(16) __nv_bfloat16 g_Wt2h[OUT_C * HID_C];
__device__ __align__(16) __nv_bfloat16 g_Wt2l[OUT_C * HID_C];

// Fused agg1+gemm2 dynamic smem layout (bytes)
#define KCP2 136                         // bf16 row stride (272B, conflict-free)
#define SM_AH 0
#define SM_AL (128 * KCP2 * 2)           // 34816
#define SM_WH (2 * 128 * KCP2 * 2)       // 69632
#define SM_WL (SM_WH + OUT_C * KCP2 * 2) // 87040
#define SM_FUSED (SM_WL + OUT_C * KCP2 * 2)  // 104448

// ---------------------------------------------------------------------------
// PTX helpers (arch-agnostic: ldmatrix sm_75+, mma bf16 sm_80+)
// ---------------------------------------------------------------------------
__device__ __forceinline__ uint32_t smem_u32(const void* p) {
    uint32_t a;
    asm("{ .reg .u64 t; cvta.to.shared.u64 t, %1; cvt.u32.u64 %0, t; }"
        : "=r"(a) : "l"(p));
    return a;
}
__device__ __forceinline__ void ldsm_x4(uint32_t* r, uint32_t addr) {
    asm volatile("ldmatrix.sync.aligned.m8n8.x4.shared.b16 {%0,%1,%2,%3}, [%4];"
                 : "=r"(r[0]), "=r"(r[1]), "=r"(r[2]), "=r"(r[3]) : "r"(addr));
}
__device__ __forceinline__ void mma_bf16(float* d, const uint32_t* a,
                                         const uint32_t* b) {
    asm volatile(
        "mma.sync.aligned.m16n8k16.row.col.f32.bf16.bf16.f32 "
        "{%0,%1,%2,%3}, {%4,%5,%6,%7}, {%8,%9}, {%0,%1,%2,%3};"
        : "+f"(d[0]), "+f"(d[1]), "+f"(d[2]), "+f"(d[3])
        : "r"(a[0]), "r"(a[1]), "r"(a[2]), "r"(a[3]), "r"(b[0]), "r"(b[1]));
}
__device__ __forceinline__ uint32_t pack2(__nv_bfloat16 lo, __nv_bfloat16 hi) {
    return ((uint32_t)__bfloat16_as_ushort(hi) << 16) | __bfloat16_as_ushort(lo);
}

// ---------------------------------------------------------------------------
// Degree / norm. edge_index is INT32 (JAX x64 disabled).
// ---------------------------------------------------------------------------
__global__ void k_count_deg(const int* __restrict__ dst) {
    int e = blockIdx.x * blockDim.x + threadIdx.x;
    if (e < EE) {
        unsigned d = (unsigned)dst[e];
        if (d < NN) atomicAdd(&g_deg[d], 1);
    }
}
__global__ void k_dinv() {
    int i = blockIdx.x * blockDim.x + threadIdx.x;
    if (i < NN) g_dinv[i] = rsqrtf((float)(g_deg[i] + 1));  // +1 self-loop
}
__global__ void k_scan_block() {
    __shared__ int sm[1024];
    int i = blockIdx.x * 1024 + threadIdx.x;
    int v = (i < NN) ? g_deg[i] : 0;
    sm[threadIdx.x] = v;
    __syncthreads();
#pragma unroll
    for (int off = 1; off < 1024; off <<= 1) {
        int t = (threadIdx.x >= off) ? sm[threadIdx.x - off] : 0;
        __syncthreads();
        sm[threadIdx.x] += t;
        __syncthreads();
    }
    int incl = sm[threadIdx.x];
    if (i < NN) g_rowptr[i] = incl - v;
    if (threadIdx.x == 1023) g_blocksums[blockIdx.x] = incl;
}
__global__ void k_scan_add() {
    int i = blockIdx.x * blockDim.x + threadIdx.x;
    if (i < NN) {
        int blk = i >> 10;
        int off = 0;
        for (int b = 0; b < blk; b++) off += g_blocksums[b];  // broadcast loads
        int r = g_rowptr[i] + off;
        g_rowptr[i] = r;
        g_cursor[i] = r;
    }
    if (i == 0) g_rowptr[NN] = EE;
}
__global__ void k_fill_csr(const int* __restrict__ src,
                           const int* __restrict__ dst) {
    int e = blockIdx.x * blockDim.x + threadIdx.x;
    if (e < EE) {
        unsigned d = (unsigned)dst[e];
        unsigned s = (unsigned)src[e];
        if (d < NN && s < NN) {
            int pos = atomicAdd(&g_cursor[d], 1);
            if ((unsigned)pos < EE) g_csr[pos] = (int)s;
        }
    }
}

// ---------------------------------------------------------------------------
// Weight split (merged W1+W2): W[K,N] fp32 -> hi/lo bf16, layout [n][k]
// ---------------------------------------------------------------------------
__global__ void k_conv(const float* __restrict__ W1, const float* __restrict__ W2) {
    int i = blockIdx.x * blockDim.x + threadIdx.x;
    constexpr int T1 = IN_C * HID_C;
    constexpr int T2 = HID_C * OUT_C;
    if (i < T1) {
        int k = i / HID_C, n = i % HID_C;
        float v = W1[i];
        __nv_bfloat16 h = __float2bfloat16(v);
        __nv_bfloat16 l = __float2bfloat16(v - __bfloat162float(h));
        g_Wt1h[(size_t)n * IN_C + k] = h;
        g_Wt1l[(size_t)n * IN_C + k] = l;
    } else if (i < T1 + T2) {
        int j = i - T1;
        int k = j / OUT_C, n = j % OUT_C;
        float v = W2[j];
        __nv_bfloat16 h = __float2bfloat16(v);
        __nv_bfloat16 l = __float2bfloat16(v - __bfloat162float(h));
        g_Wt2h[(size_t)n * HID_C + k] = h;
        g_Wt2l[(size_t)n * HID_C + k] = l;
    }
}

// ---------------------------------------------------------------------------
// gemm1: bf16x3 HMMA with register-prefetch pipeline (unchanged from R12).
// ---------------------------------------------------------------------------
template <int K, int N>
__device__ __forceinline__ void mma_gemm_core(
        const float* __restrict__ A,
        const __nv_bfloat16* __restrict__ Wth,
        const __nv_bfloat16* __restrict__ Wtl,
        float* __restrict__ C) {
    constexpr int KC  = 32;
    constexpr int KCP = 40;
    constexpr int KCH = K / KC;
    constexpr int WU  = N / 64;
    __shared__ __align__(16) __nv_bfloat16 sAh[128 * KCP];
    __shared__ __align__(16) __nv_bfloat16 sAl[128 * KCP];
    __shared__ __align__(16) __nv_bfloat16 sWh[N * KCP];
    __shared__ __align__(16) __nv_bfloat16 sWl[N * KCP];

    const int tid  = threadIdx.x;
    const int lane = tid & 31;
    const int warp = tid >> 5;
    const int wrow = warp * 16;
    const int rowBase = blockIdx.x * 128;

    const uint32_t sAh_b = smem_u32(sAh), sAl_b = smem_u32(sAl);
    const uint32_t sWh_b = smem_u32(sWh), sWl_b = smem_u32(sWl);

    float acc[N / 8][4];
#pragma unroll
    for (int t = 0; t < N / 8; t++)
#pragma unroll
        for (int q = 0; q < 4; q++) acc[t][q] = 0.f;

    const int g  = lane >> 3;
    const int r8 = lane & 7;

    float4 pa[4];
    uint4  pwh[WU], pwl[WU];

    auto loadA = [&](int c) {
#pragma unroll
        for (int u = 0; u < 4; u++) {
            int i = tid + u * 256;
            int r = i >> 3, kq = i & 7;
            int grow = rowBase + r;
            pa[u] = make_float4(0.f, 0.f, 0.f, 0.f);
            if (grow < NN)
                pa[u] = *reinterpret_cast<const float4*>(
                            A + (size_t)grow * K + c * KC + kq * 4);
        }
    };
    auto loadW = [&](int c) {
#pragma unroll
        for (int u = 0; u < WU; u++) {
            int i = tid + u * 256;
            int n = i >> 2, q = i & 3;
            pwh[u] = *reinterpret_cast<const uint4*>(
                         Wth + (size_t)n * K + c * KC + q * 8);
            pwl[u] = *reinterpret_cast<const uint4*>(
                         Wtl + (size_t)n * K + c * KC + q * 8);
        }
    };
    auto storeAW = [&]() {
#pragma unroll
        for (int u = 0; u < 4; u++) {
            int i = tid + u * 256;
            int r = i >> 3, kq = i & 7;
            float4 v = pa[u];
            __nv_bfloat16 hx = __float2bfloat16(v.x), hy = __float2bfloat16(v.y);
            __nv_bfloat16 hz = __float2bfloat16(v.z), hw = __float2bfloat16(v.w);
            __nv_bfloat16 lx = __float2bfloat16(v.x - __bfloat162float(hx));
            __nv_bfloat16 ly = __float2bfloat16(v.y - __bfloat162float(hy));
            __nv_bfloat16 lz = __float2bfloat16(v.z - __bfloat162float(hz));
            __nv_bfloat16 lw = __float2bfloat16(v.w - __bfloat162float(hw));
            *reinterpret_cast<uint2*>(&sAh[r * KCP + kq * 4]) =
                make_uint2(pack2(hx, hy), pack2(hz, hw));
            *reinterpret_cast<uint2*>(&sAl[r * KCP + kq * 4]) =
                make_uint2(pack2(lx, ly), pack2(lz, lw));
        }
#pragma unroll
        for (int u = 0; u < WU; u++) {
            int i = tid + u * 256;
            int n = i >> 2, q = i & 3;
            *reinterpret_cast<uint4*>(&sWh[n * KCP + q * 8]) = pwh[u];
            *reinterpret_cast<uint4*>(&sWl[n * KCP + q * 8]) = pwl[u];
        }
    };

    loadA(0);
    loadW(0);

    for (int c = 0; c < KCH; c++) {
        if (c) __syncthreads();
        storeAW();
        __syncthreads();
        if (c + 1 < KCH) {
            loadA(c + 1);
            loadW(c + 1);
        }

#pragma unroll
        for (int ks = 0; ks < KC / 16; ks++) {
            int k0 = ks * 16;
            uint32_t ah[4], al[4];
            {
                int arow = wrow + r8 + ((g & 1) << 3);
                int acol = k0 + ((g >> 1) << 3);
                uint32_t off = (uint32_t)(arow * KCP + acol) * 2;
                ldsm_x4(ah, sAh_b + off);
                ldsm_x4(al, sAl_b + off);
            }
#pragma unroll
            for (int np = 0; np < N / 16; np++) {
                int nrow = np * 16 + r8 + ((g >> 1) << 3);
                int kcol = k0 + ((g & 1) << 3);
                uint32_t boff = (uint32_t)(nrow * KCP + kcol) * 2;
                uint32_t bh[4], bl[4];
                ldsm_x4(bh, sWh_b + boff);
                ldsm_x4(bl, sWl_b + boff);
                mma_bf16(acc[2 * np],     ah, bh);
                mma_bf16(acc[2 * np],     ah, bl);
                mma_bf16(acc[2 * np],     al, bh);
                mma_bf16(acc[2 * np + 1], ah, bh + 2);
                mma_bf16(acc[2 * np + 1], ah, bl + 2);
                mma_bf16(acc[2 * np + 1], al, bh + 2);
            }
        }
    }

    int r0 = rowBase + wrow + (lane >> 2);
    int r1 = r0 + 8;
    int cbase = (lane & 3) * 2;
    float s0 = (r0 < NN) ? g_dinv[r0] : 0.f;
    float s1 = (r1 < NN) ? g_dinv[r1] : 0.f;
#pragma unroll
    for (int t = 0; t < N / 8; t++) {
        int col = t * 8 + cbase;
        if (r0 < NN)
            *reinterpret_cast<float2*>(C + (size_t)r0 * N + col) =
                make_float2(acc[t][0] * s0, acc[t][1] * s0);
        if (r1 < NN)
            *reinterpret_cast<float2*>(C + (size_t)r1 * N + col) =
                make_float2(acc[t][2] * s1, acc[t][3] * s1);
    }
}

__global__ void __launch_bounds__(256)
k_gemm1(const float* __restrict__ x) {
    mma_gemm_core<IN_C, HID_C>(x, g_Wt1h, g_Wt1l, g_h1);
}

// ---------------------------------------------------------------------------
// FUSED agg1 + gemm2.  Block = 128 nodes, 256 threads, 104KB dynamic smem.
//   Phase 1: per node, gather-aggregate h1 (self + neighbors), apply
//            dinv*(.)+b1, ReLU, split bf16 hi/lo DIRECTLY into smem A tile.
//            Also re-zeroes g_deg (deterministic replay invariant).
//   Phase 2: HMMA bf16x3 over K=HID_C from smem; h2 = (t1@W2)*dinv[row].
// ---------------------------------------------------------------------------
__global__ void __launch_bounds__(256)
k_agg1_gemm2(const float* __restrict__ b1) {
    extern __shared__ __align__(16) char dyn[];
    __nv_bfloat16* sAh = reinterpret_cast<__nv_bfloat16*>(dyn + SM_AH);
    __nv_bfloat16* sAl = reinterpret_cast<__nv_bfloat16*>(dyn + SM_AL);
    __nv_bfloat16* sWh = reinterpret_cast<__nv_bfloat16*>(dyn + SM_WH);
    __nv_bfloat16* sWl = reinterpret_cast<__nv_bfloat16*>(dyn + SM_WL);

    const int tid  = threadIdx.x;
    const int lane = tid & 31;
    const int warp = tid >> 5;
    const int rowBase = blockIdx.x * 128;

    // --- copy W2 images (64 x 128 bf16 each) into padded smem ---
#pragma unroll
    for (int u = 0; u < 4; u++) {
        int i = tid + u * 256;            // [0, 1024): n = i/16, q = i%16
        int n = i >> 4, q = i & 15;
        *reinterpret_cast<uint4*>(&sWh[n * KCP2 + q * 8]) =
            *reinterpret_cast<const uint4*>(g_Wt2h + (size_t)n * HID_C + q * 8);
        *reinterpret_cast<uint4*>(&sWl[n * KCP2 + q * 8]) =
            *reinterpret_cast<const uint4*>(g_Wt2l + (size_t)n * HID_C + q * 8);
    }

    // --- phase 1: aggregate (warp w handles nodes rowBase + w + 8*it) ---
    const float4* h1v = reinterpret_cast<const float4*>(g_h1);
    const float4  bv  = reinterpret_cast<const float4*>(b1)[lane];
#pragma unroll 1
    for (int it = 0; it < 16; it++) {
        int local = warp + it * 8;          // 0..127
        int node  = rowBase + local;
        float4 acc = make_float4(0.f, 0.f, 0.f, 0.f);
        if (node < NN) {
            acc = h1v[(size_t)node * 32 + lane];   // self-loop
            const int beg = g_rowptr[node];
            const int end = g_rowptr[node + 1];
#pragma unroll 4
            for (int e = beg; e < end; e++) {
                int s = g_csr[e];
                float4 v = h1v[(size_t)s * 32 + lane];
                acc.x += v.x; acc.y += v.y; acc.z += v.z; acc.w += v.w;
            }
            const float d = g_dinv[node];
            acc.x = fmaxf(acc.x * d + bv.x, 0.f);
            acc.y = fmaxf(acc.y * d + bv.y, 0.f);
            acc.z = fmaxf(acc.z * d + bv.z, 0.f);
            acc.w = fmaxf(acc.w * d + bv.w, 0.f);
            if (lane == 0) g_deg[node] = 0;        // reset for next replay
        }
        __nv_bfloat16 hx = __float2bfloat16(acc.x), hy = __float2bfloat16(acc.y);
        __nv_bfloat16 hz = __float2bfloat16(acc.z), hw = __float2bfloat16(acc.w);
        __nv_bfloat16 lx = __float2bfloat16(acc.x - __bfloat162float(hx));
        __nv_bfloat16 ly = __float2bfloat16(acc.y - __bfloat162float(hy));
        __nv_bfloat16 lz = __float2bfloat16(acc.z - __bfloat162float(hz));
        __nv_bfloat16 lw = __float2bfloat16(acc.w - __bfloat162float(hw));
        *reinterpret_cast<uint2*>(&sAh[local * KCP2 + lane * 4]) =
            make_uint2(pack2(hx, hy), pack2(hz, hw));
        *reinterpret_cast<uint2*>(&sAl[local * KCP2 + lane * 4]) =
            make_uint2(pack2(lx, ly), pack2(lz, lw));
    }
    __syncthreads();

    // --- phase 2: HMMA, K = 128, N = 64 ---
    constexpr int N = OUT_C;
    const uint32_t sAh_b = smem_u32(sAh), sAl_b = smem_u32(sAl);
    const uint32_t sWh_b = smem_u32(sWh), sWl_b = smem_u32(sWl);
    const int wrow = warp * 16;
    const int g  = lane >> 3;
    const int r8 = lane & 7;

    float acc[N / 8][4];
#pragma unroll
    for (int t = 0; t < N / 8; t++)
#pragma unroll
        for (int q = 0; q < 4; q++) acc[t][q] = 0.f;

#pragma unroll
    for (int ks = 0; ks < HID_C / 16; ks++) {
        int k0 = ks * 16;
        uint32_t ah[4], al[4];
        {
            int arow = wrow + r8 + ((g & 1) << 3);
            int acol = k0 + ((g >> 1) << 3);
            uint32_t off = (uint32_t)(arow * KCP2 + acol) * 2;
            ldsm_x4(ah, sAh_b + off);
            ldsm_x4(al, sAl_b + off);
        }
#pragma unroll
        for (int np = 0; np < N / 16; np++) {
            int nrow = np * 16 + r8 + ((g >> 1) << 3);
            int kcol = k0 + ((g & 1) << 3);
            uint32_t boff = (uint32_t)(nrow * KCP2 + kcol) * 2;
            uint32_t bh[4], bl[4];
            ldsm_x4(bh, sWh_b + boff);
            ldsm_x4(bl, sWl_b + boff);
            mma_bf16(acc[2 * np],     ah, bh);
            mma_bf16(acc[2 * np],     ah, bl);
            mma_bf16(acc[2 * np],     al, bh);
            mma_bf16(acc[2 * np + 1], ah, bh + 2);
            mma_bf16(acc[2 * np + 1], ah, bl + 2);
            mma_bf16(acc[2 * np + 1], al, bh + 2);
        }
    }

    // epilogue: h2 = acc * dinv[row]
    int r0 = rowBase + wrow + (lane >> 2);
    int r1 = r0 + 8;
    int cbase = (lane & 3) * 2;
    float s0 = (r0 < NN) ? g_dinv[r0] : 0.f;
    float s1 = (r1 < NN) ? g_dinv[r1] : 0.f;
#pragma unroll
    for (int t = 0; t < N / 8; t++) {
        int col = t * 8 + cbase;
        if (r0 < NN)
            *reinterpret_cast<float2*>(g_h2 + (size_t)r0 * N + col) =
                make_float2(acc[t][0] * s0, acc[t][1] * s0);
        if (r1 < NN)
            *reinterpret_cast<float2*>(g_h2 + (size_t)r1 * N + col) =
                make_float2(acc[t][2] * s1, acc[t][3] * s1);
    }
}

// ---------------------------------------------------------------------------
// agg2: out[i] = dinv[i] * (h2[i] + sum_neigh h2[s]) + b2
// ---------------------------------------------------------------------------
__global__ void __launch_bounds__(128)
k_agg2(const float* __restrict__ b2, float* __restrict__ out) {
    constexpr int G   = OUT_C / 4;   // 16 threads per node
    constexpr int NPB = 128 / G;     // 8 nodes per block
    const int local = threadIdx.x / G;
    const int lane  = threadIdx.x % G;
    const int node  = blockIdx.x * NPB + local;
    if (node >= NN) return;

    const float4* base = reinterpret_cast<const float4*>(g_h2);
    float4 acc = base[(size_t)node * G + lane];
    const int beg = g_rowptr[node];
    const int end = g_rowptr[node + 1];
#pragma unroll 4
    for (int e = beg; e < end; e++) {
        int s = g_csr[e];
        float4 v = base[(size_t)s * G + lane];
        acc.x += v.x; acc.y += v.y; acc.z += v.z; acc.w += v.w;
    }
    const float d = g_dinv[node];
    float4 b = reinterpret_cast<const float4*>(b2)[lane];
    acc.x = acc.x * d + b.x;
    acc.y = acc.y * d + b.y;
    acc.z = acc.z * d + b.z;
    acc.w = acc.w * d + b.w;
    reinterpret_cast<float4*>(out)[(size_t)node * G + lane] = acc;
}

// ---------------------------------------------------------------------------
// Streams/events + smem opt-in, created once at process init (outside capture)
// ---------------------------------------------------------------------------
struct StreamBundle {
    cudaStream_t s1;
    cudaEvent_t  ev_start, ev_deg, ev_gemm1;
    StreamBundle() {
        cudaStreamCreateWithFlags(&s1, cudaStreamNonBlocking);
        cudaEventCreateWithFlags(&ev_start, cudaEventDisableTiming);
        cudaEventCreateWithFlags(&ev_deg,   cudaEventDisableTiming);
        cudaEventCreateWithFlags(&ev_gemm1, cudaEventDisableTiming);
        cudaFuncSetAttribute(k_agg1_gemm2,
                             cudaFuncAttributeMaxDynamicSharedMemorySize,
                             SM_FUSED);
    }
};
static StreamBundle g_sb;

// ---------------------------------------------------------------------------
// Launch: fork-join across two streams (capture-legal event fork).
//   s0: count -> [ev_deg] -> scan_block -> scan_add -> fill_csr
//       -> wait(ev_gemm1) -> agg1_gemm2 -> agg2
//   s1: wait(ev_start) -> conv -> wait(ev_deg) -> dinv -> gemm1 -> [ev_gemm1]
// ---------------------------------------------------------------------------
extern "C" void kernel_launch(void* const* d_in, const int* in_sizes, int n_in,
                              void* d_out, int out_size) {
    const float* x   = (const float*)d_in[0];
    const int*   ei  = (const int*)d_in[1];     // int32 edge_index
    const float* W1  = (const float*)d_in[2];
    const float* b1  = (const float*)d_in[3];
    const float* W2  = (const float*)d_in[4];
    const float* b2  = (const float*)d_in[5];
    float*       out = (float*)d_out;

    const int* src = ei;
    const int* dst = ei + EE;

    const int TB = 256;
    const int nBlkN = (NN + TB - 1) / TB;
    const int nBlkE = (EE + TB - 1) / TB;
    const int nScan = (NN + 1023) / 1024;
    const int nTiles = (NN + 127) / 128;   // 391

    cudaStream_t s0 = 0;            // harness-captured (legacy) stream
    cudaStream_t s1 = g_sb.s1;

    // fork s1 off the captured stream
    cudaEventRecord(g_sb.ev_start, s0);
    cudaStreamWaitEvent(s1, g_sb.ev_start, 0);

    // s1: weight images (no deps)
    {
        constexpr int TOT = IN_C * HID_C + HID_C * OUT_C;
        k_conv<<<(TOT + 255) / 256, 256, 0, s1>>>(W1, W2);
    }

    // s0: degree (g_deg zeroed by previous call's fused kernel / module init)
    k_count_deg<<<nBlkE, TB, 0, s0>>>(dst);
    cudaEventRecord(g_sb.ev_deg, s0);

    // s0: scan + csr
    k_scan_block<<<nScan, 1024, 0, s0>>>();
    k_scan_add<<<nBlkN, TB, 0, s0>>>();
    k_fill_csr<<<nBlkE, TB, 0, s0>>>(src, dst);

    // s1: dinv (needs deg) then gemm1 (needs x, W images, dinv)
    cudaStreamWaitEvent(s1, g_sb.ev_deg, 0);
    k_dinv<<<nBlkN, TB, 0, s1>>>();
    k_gemm1<<<nTiles, 256, 0, s1>>>(x);
    cudaEventRecord(g_sb.ev_gemm1, s1);

    // join: fused agg1+gemm2 needs csr (s0) + h1 (s1); also re-zeroes deg
    cudaStreamWaitEvent(s0, g_sb.ev_gemm1, 0);
    k_agg1_gemm2<<<nTiles, 256, SM_FUSED, s0>>>(b1);

    // agg2
    {
        constexpr int NPB = 128 / (OUT_C / 4);
        int grid = (NN + NPB - 1) / NPB;
        k_agg2<<<grid, 128, 0, s0>>>(b2, out);
    }
}

// round 15
// speedup vs baseline: 1.3488x; 1.3488x over previous
#include <cuda_runtime.h>
#include <cuda_bf16.h>
#include <cstdint>

// Problem constants (fixed by the dataset)
#define NN 50000
#define EE 800000
#define IN_C 256
#define HID_C 128
#define OUT_C 64
#define NSCAN 49   // ceil(NN / 1024)

// ---------------------------------------------------------------------------
// Scratch (device globals). All float4-accessed buffers 16B-aligned.
// ---------------------------------------------------------------------------
__device__ int   g_deg[NN];
__device__ int   g_rowptr[NN + 1];
__device__ int   g_cursor[NN];
__device__ int   g_sagg[64];     // per-block scan aggregates
__device__ int   g_sflag[64];    // 0 = not published, 1 = aggregate ready
__device__ int   g_csr[EE];
__device__ __align__(16) float g_h1[(size_t)NN * HID_C];
__device__ __align__(16) float g_t1[(size_t)NN * HID_C];
__device__ __align__(16) float g_h2[(size_t)NN * OUT_C];
// Weight images: W^T in bf16 hi/lo, row-major [n][k] (k contiguous)
__device__ __align__(16) __nv_bfloat16 g_Wt1h[HID_C * IN_C];
__device__ __align__(16) __nv_bfloat16 g_Wt1l[HID_C * IN_C];
__device__ __align__(16) __nv_bfloat16 g_Wt2h[OUT_C * HID_C];
__device__ __align__(16) __nv_bfloat16 g_Wt2l[OUT_C * HID_C];

// ---------------------------------------------------------------------------
// Side stream + events for fork-join overlap (created once at process init).
// ---------------------------------------------------------------------------
struct StreamBundle {
    cudaStream_t s1;
    cudaEvent_t  ev_start, ev_deg, ev_gemm1;
    StreamBundle() {
        cudaStreamCreateWithFlags(&s1, cudaStreamNonBlocking);
        cudaEventCreateWithFlags(&ev_start, cudaEventDisableTiming);
        cudaEventCreateWithFlags(&ev_deg,   cudaEventDisableTiming);
        cudaEventCreateWithFlags(&ev_gemm1, cudaEventDisableTiming);
    }
};
static StreamBundle g_sb;

// ---------------------------------------------------------------------------
// PTX helpers (arch-agnostic: ldmatrix sm_75+, mma bf16 sm_80+)
// ---------------------------------------------------------------------------
__device__ __forceinline__ uint32_t smem_u32(const void* p) {
    uint32_t a;
    asm("{ .reg .u64 t; cvta.to.shared.u64 t, %1; cvt.u32.u64 %0, t; }"
        : "=r"(a) : "l"(p));
    return a;
}
__device__ __forceinline__ void ldsm_x4(uint32_t* r, uint32_t addr) {
    asm volatile("ldmatrix.sync.aligned.m8n8.x4.shared.b16 {%0,%1,%2,%3}, [%4];"
                 : "=r"(r[0]), "=r"(r[1]), "=r"(r[2]), "=r"(r[3]) : "r"(addr));
}
__device__ __forceinline__ void mma_bf16(float* d, const uint32_t* a,
                                         const uint32_t* b) {
    asm volatile(
        "mma.sync.aligned.m16n8k16.row.col.f32.bf16.bf16.f32 "
        "{%0,%1,%2,%3}, {%4,%5,%6,%7}, {%8,%9}, {%0,%1,%2,%3};"
        : "+f"(d[0]), "+f"(d[1]), "+f"(d[2]), "+f"(d[3])
        : "r"(a[0]), "r"(a[1]), "r"(a[2]), "r"(a[3]), "r"(b[0]), "r"(b[1]));
}
__device__ __forceinline__ uint32_t pack2(__nv_bfloat16 lo, __nv_bfloat16 hi) {
    return ((uint32_t)__bfloat16_as_ushort(hi) << 16) | __bfloat16_as_ushort(lo);
}
__device__ __forceinline__ float dinv_of(int node) {
    return rsqrtf((float)(g_deg[node] + 1));   // +1 self-loop
}

// ---------------------------------------------------------------------------
// Degree / norm. edge_index is INT32 (JAX x64 disabled).
// ---------------------------------------------------------------------------
__global__ void k_clear_deg() {
    int i = blockIdx.x * blockDim.x + threadIdx.x;
    if (i < NN) g_deg[i] = 0;
    if (i < 64) g_sflag[i] = 0;      // reset scan flags for this replay
}
__global__ void k_count_deg(const int* __restrict__ dst) {
    int e = blockIdx.x * blockDim.x + threadIdx.x;
    if (e < EE) {
        unsigned d = (unsigned)dst[e];
        if (d < NN) atomicAdd(&g_deg[d], 1);
    }
}

// ---------------------------------------------------------------------------
// Single-pass exclusive scan of g_deg -> g_rowptr/g_cursor.
//   49 blocks x 1024 (all co-resident). Each block: local inclusive scan,
//   publish aggregate (fence+flag), parallel spin-read of ALL predecessor
//   aggregates (threads tid<bid), block-reduce -> offset. Deterministic.
// ---------------------------------------------------------------------------
__global__ void k_scan() {
    __shared__ int sm[1024];
    __shared__ int spre[64];
    __shared__ int s_off;
    const int tid = threadIdx.x;
    const int bid = blockIdx.x;
    const int i = bid * 1024 + tid;

    int v = (i < NN) ? g_deg[i] : 0;
    sm[tid] = v;
    __syncthreads();
#pragma unroll
    for (int off = 1; off < 1024; off <<= 1) {
        int t = (tid >= off) ? sm[tid - off] : 0;
        __syncthreads();
        sm[tid] += t;
        __syncthreads();
    }
    int incl = sm[tid];

    // publish own aggregate first (so no block can deadlock on us)
    if (tid == 1023) {
        g_sagg[bid] = incl;
        __threadfence();
        atomicExch(&g_sflag[bid], 1);
    }
    // parallel lookback: thread tid reads predecessor tid's aggregate
    if (tid < 64) {
        int val = 0;
        if (tid < bid) {
            while (atomicAdd(&g_sflag[tid], 0) == 0) { }
            val = atomicAdd(&g_sagg[tid], 0);
        }
        spre[tid] = val;
    }
    __syncthreads();
    if (tid == 0) {
        int o = 0;
#pragma unroll
        for (int b = 0; b < 64; b++) o += spre[b];
        s_off = o;
    }
    __syncthreads();
    const int off = s_off;
    if (i < NN) {
        int r = incl - v + off;     // exclusive prefix
        g_rowptr[i] = r;
        g_cursor[i] = r;
    }
    if (i == 0) g_rowptr[NN] = EE;
}

__global__ void k_fill_csr(const int* __restrict__ src,
                           const int* __restrict__ dst) {
    int e = blockIdx.x * blockDim.x + threadIdx.x;
    if (e < EE) {
        unsigned d = (unsigned)dst[e];
        unsigned s = (unsigned)src[e];
        if (d < NN && s < NN) {
            int pos = atomicAdd(&g_cursor[d], 1);
            if ((unsigned)pos < EE) g_csr[pos] = (int)s;
        }
    }
}

// ---------------------------------------------------------------------------
// Weight split (merged W1+W2): W[K,N] fp32 -> hi/lo bf16, layout [n][k]
// ---------------------------------------------------------------------------
__global__ void k_conv(const float* __restrict__ W1, const float* __restrict__ W2) {
    int i = blockIdx.x * blockDim.x + threadIdx.x;
    constexpr int T1 = IN_C * HID_C;
    constexpr int T2 = HID_C * OUT_C;
    if (i < T1) {
        int k = i / HID_C, n = i % HID_C;
        float v = W1[i];
        __nv_bfloat16 h = __float2bfloat16(v);
        __nv_bfloat16 l = __float2bfloat16(v - __bfloat162float(h));
        g_Wt1h[(size_t)n * IN_C + k] = h;
        g_Wt1l[(size_t)n * IN_C + k] = l;
    } else if (i < T1 + T2) {
        int j = i - T1;
        int k = j / OUT_C, n = j % OUT_C;
        float v = W2[j];
        __nv_bfloat16 h = __float2bfloat16(v);
        __nv_bfloat16 l = __float2bfloat16(v - __bfloat162float(h));
        g_Wt2h[(size_t)n * HID_C + k] = h;
        g_Wt2l[(size_t)n * HID_C + k] = l;
    }
}

// ---------------------------------------------------------------------------
// bf16x3 HMMA GEMM with register-prefetch pipeline:
//   C[row,:] = (A[row,:] @ W) * rsqrt(deg[row]+1)
// ---------------------------------------------------------------------------
template <int K, int N>
__device__ __forceinline__ void mma_gemm_core(
        const float* __restrict__ A,
        const __nv_bfloat16* __restrict__ Wth,
        const __nv_bfloat16* __restrict__ Wtl,
        float* __restrict__ C) {
    constexpr int KC  = 32;
    constexpr int KCP = 40;
    constexpr int KCH = K / KC;
    constexpr int WU  = N / 64;
    __shared__ __align__(16) __nv_bfloat16 sAh[128 * KCP];
    __shared__ __align__(16) __nv_bfloat16 sAl[128 * KCP];
    __shared__ __align__(16) __nv_bfloat16 sWh[N * KCP];
    __shared__ __align__(16) __nv_bfloat16 sWl[N * KCP];

    const int tid  = threadIdx.x;
    const int lane = tid & 31;
    const int warp = tid >> 5;
    const int wrow = warp * 16;
    const int rowBase = blockIdx.x * 128;

    const uint32_t sAh_b = smem_u32(sAh), sAl_b = smem_u32(sAl);
    const uint32_t sWh_b = smem_u32(sWh), sWl_b = smem_u32(sWl);

    float acc[N / 8][4];
#pragma unroll
    for (int t = 0; t < N / 8; t++)
#pragma unroll
        for (int q = 0; q < 4; q++) acc[t][q] = 0.f;

    const int g  = lane >> 3;
    const int r8 = lane & 7;

    float4 pa[4];
    uint4  pwh[WU], pwl[WU];

    auto loadA = [&](int c) {
#pragma unroll
        for (int u = 0; u < 4; u++) {
            int i = tid + u * 256;
            int r = i >> 3, kq = i & 7;
            int grow = rowBase + r;
            pa[u] = make_float4(0.f, 0.f, 0.f, 0.f);
            if (grow < NN)
                pa[u] = *reinterpret_cast<const float4*>(
                            A + (size_t)grow * K + c * KC + kq * 4);
        }
    };
    auto loadW = [&](int c) {
#pragma unroll
        for (int u = 0; u < WU; u++) {
            int i = tid + u * 256;
            int n = i >> 2, q = i & 3;
            pwh[u] = *reinterpret_cast<const uint4*>(
                         Wth + (size_t)n * K + c * KC + q * 8);
            pwl[u] = *reinterpret_cast<const uint4*>(
                         Wtl + (size_t)n * K + c * KC + q * 8);
        }
    };
    auto storeAW = [&]() {
#pragma unroll
        for (int u = 0; u < 4; u++) {
            int i = tid + u * 256;
            int r = i >> 3, kq = i & 7;
            float4 v = pa[u];
            __nv_bfloat16 hx = __float2bfloat16(v.x), hy = __float2bfloat16(v.y);
            __nv_bfloat16 hz = __float2bfloat16(v.z), hw = __float2bfloat16(v.w);
            __nv_bfloat16 lx = __float2bfloat16(v.x - __bfloat162float(hx));
            __nv_bfloat16 ly = __float2bfloat16(v.y - __bfloat162float(hy));
            __nv_bfloat16 lz = __float2bfloat16(v.z - __bfloat162float(hz));
            __nv_bfloat16 lw = __float2bfloat16(v.w - __bfloat162float(hw));
            *reinterpret_cast<uint2*>(&sAh[r * KCP + kq * 4]) =
                make_uint2(pack2(hx, hy), pack2(hz, hw));
            *reinterpret_cast<uint2*>(&sAl[r * KCP + kq * 4]) =
                make_uint2(pack2(lx, ly), pack2(lz, lw));
        }
#pragma unroll
        for (int u = 0; u < WU; u++) {
            int i = tid + u * 256;
            int n = i >> 2, q = i & 3;
            *reinterpret_cast<uint4*>(&sWh[n * KCP + q * 8]) = pwh[u];
            *reinterpret_cast<uint4*>(&sWl[n * KCP + q * 8]) = pwl[u];
        }
    };

    loadA(0);
    loadW(0);

    for (int c = 0; c < KCH; c++) {
        if (c) __syncthreads();
        storeAW();
        __syncthreads();
        if (c + 1 < KCH) {
            loadA(c + 1);
            loadW(c + 1);
        }

#pragma unroll
        for (int ks = 0; ks < KC / 16; ks++) {
            int k0 = ks * 16;
            uint32_t ah[4], al[4];
            {
                int arow = wrow + r8 + ((g & 1) << 3);
                int acol = k0 + ((g >> 1) << 3);
                uint32_t off = (uint32_t)(arow * KCP + acol) * 2;
                ldsm_x4(ah, sAh_b + off);
                ldsm_x4(al, sAl_b + off);
            }
#pragma unroll
            for (int np = 0; np < N / 16; np++) {
                int nrow = np * 16 + r8 + ((g >> 1) << 3);
                int kcol = k0 + ((g & 1) << 3);
                uint32_t boff = (uint32_t)(nrow * KCP + kcol) * 2;
                uint32_t bh[4], bl[4];
                ldsm_x4(bh, sWh_b + boff);
                ldsm_x4(bl, sWl_b + boff);
                mma_bf16(acc[2 * np],     ah, bh);
                mma_bf16(acc[2 * np],     ah, bl);
                mma_bf16(acc[2 * np],     al, bh);
                mma_bf16(acc[2 * np + 1], ah, bh + 2);
                mma_bf16(acc[2 * np + 1], ah, bl + 2);
                mma_bf16(acc[2 * np + 1], al, bh + 2);
            }
        }
    }

    int r0 = rowBase + wrow + (lane >> 2);
    int r1 = r0 + 8;
    int cbase = (lane & 3) * 2;
    float s0 = (r0 < NN) ? dinv_of(r0) : 0.f;
    float s1 = (r1 < NN) ? dinv_of(r1) : 0.f;
#pragma unroll
    for (int t = 0; t < N / 8; t++) {
        int col = t * 8 + cbase;
        if (r0 < NN)
            *reinterpret_cast<float2*>(C + (size_t)r0 * N + col) =
                make_float2(acc[t][0] * s0, acc[t][1] * s0);
        if (r1 < NN)
            *reinterpret_cast<float2*>(C + (size_t)r1 * N + col) =
                make_float2(acc[t][2] * s1, acc[t][3] * s1);
    }
}

__global__ void __launch_bounds__(256)
k_gemm1(const float* __restrict__ x) {
    mma_gemm_core<IN_C, HID_C>(x, g_Wt1h, g_Wt1l, g_h1);
}
__global__ void __launch_bounds__(256)
k_gemm2() {
    mma_gemm_core<HID_C, OUT_C>(g_t1, g_Wt2h, g_Wt2l, g_h2);
}

// ---------------------------------------------------------------------------
// Aggregation: out[i] = act( dinv[i] * (hs[i] + sum_{s in N(i)} hs[s]) + b )
// ---------------------------------------------------------------------------
template <int C, bool RELU>
__device__ __forceinline__ void aggregate_core(
        const float* __restrict__ hs, const float* __restrict__ bias,
        float* __restrict__ out) {
    constexpr int G   = C / 4;
    constexpr int NPB = 128 / G;
    const int local = threadIdx.x / G;
    const int lane  = threadIdx.x % G;
    const int node  = blockIdx.x * NPB + local;
    if (node >= NN) return;

    const float4* base = reinterpret_cast<const float4*>(hs);
    float4 acc = base[(size_t)node * G + lane];
    const int beg = g_rowptr[node];
    const int end = g_rowptr[node + 1];
#pragma unroll 4
    for (int e = beg; e < end; e++) {
        int s = g_csr[e];
        float4 v = base[(size_t)s * G + lane];
        acc.x += v.x; acc.y += v.y; acc.z += v.z; acc.w += v.w;
    }
    const float d = dinv_of(node);
    float4 b = reinterpret_cast<const float4*>(bias)[lane];
    acc.x = acc.x * d + b.x;
    acc.y = acc.y * d + b.y;
    acc.z = acc.z * d + b.z;
    acc.w = acc.w * d + b.w;
    if (RELU) {
        acc.x = fmaxf(acc.x, 0.f);
        acc.y = fmaxf(acc.y, 0.f);
        acc.z = fmaxf(acc.z, 0.f);
        acc.w = fmaxf(acc.w, 0.f);
    }
    reinterpret_cast<float4*>(out)[(size_t)node * G + lane] = acc;
}

__global__ void __launch_bounds__(128)
k_agg1(const float* __restrict__ b1) {
    aggregate_core<HID_C, true>(g_h1, b1, g_t1);
}
__global__ void __launch_bounds__(128)
k_agg2(const float* __restrict__ b2, float* __restrict__ out) {
    aggregate_core<OUT_C, false>(g_h2, b2, out);
}

// ---------------------------------------------------------------------------
// Launch: fork-join across two streams (capture-legal event fork). 9 kernels.
//   s0: clear -> count -> [ev_deg] -> scan -> fill_csr
//       -> wait(ev_gemm1) -> agg1 -> gemm2 -> agg2
//   s1: wait(ev_start) -> conv -> wait(ev_deg) -> gemm1 -> [ev_gemm1]
// ---------------------------------------------------------------------------
extern "C" void kernel_launch(void* const* d_in, const int* in_sizes, int n_in,
                              void* d_out, int out_size) {
    const float* x   = (const float*)d_in[0];
    const int*   ei  = (const int*)d_in[1];     // int32 edge_index
    const float* W1  = (const float*)d_in[2];
    const float* b1  = (const float*)d_in[3];
    const float* W2  = (const float*)d_in[4];
    const float* b2  = (const float*)d_in[5];
    float*       out = (float*)d_out;

    const int* src = ei;
    const int* dst = ei + EE;

    const int TB = 256;
    const int nBlkN = (NN + TB - 1) / TB;
    const int nBlkE = (EE + TB - 1) / TB;
    const int nTiles = (NN + 127) / 128;   // 391

    cudaStream_t s0 = 0;            // harness-captured (legacy) stream
    cudaStream_t s1 = g_sb.s1;

    // fork s1 off the captured stream
    cudaEventRecord(g_sb.ev_start, s0);
    cudaStreamWaitEvent(s1, g_sb.ev_start, 0);

    // s1: weight images (no deps)
    {
        constexpr int TOT = IN_C * HID_C + HID_C * OUT_C;
        k_conv<<<(TOT + 255) / 256, 256, 0, s1>>>(W1, W2);
    }

    // s0: degree
    k_clear_deg<<<nBlkN, TB, 0, s0>>>();
    k_count_deg<<<nBlkE, TB, 0, s0>>>(dst);
    cudaEventRecord(g_sb.ev_deg, s0);

    // s0: single-pass scan + csr fill
    k_scan<<<NSCAN, 1024, 0, s0>>>();
    k_fill_csr<<<nBlkE, TB, 0, s0>>>(src, dst);

    // s1: gemm1 (needs x, W images, deg for epilogue dinv)
    cudaStreamWaitEvent(s1, g_sb.ev_deg, 0);
    k_gemm1<<<nTiles, 256, 0, s1>>>(x);
    cudaEventRecord(g_sb.ev_gemm1, s1);

    // join: agg1 needs csr (s0) + h1 (s1)
    cudaStreamWaitEvent(s0, g_sb.ev_gemm1, 0);
    {
        constexpr int NPB = 128 / (HID_C / 4);
        int grid = (NN + NPB - 1) / NPB;
        k_agg1<<<grid, 128, 0, s0>>>(b1);
    }
    k_gemm2<<<nTiles, 256, 0, s0>>>();
    {
        constexpr int NPB = 128 / (OUT_C / 4);
        int grid = (NN + NPB - 1) / NPB;
        k_agg2<<<grid, 128, 0, s0>>>(b2, out);
    }
}

// round 16
// speedup vs baseline: 1.4214x; 1.0538x over previous
#include <cuda_runtime.h>
#include <cuda_bf16.h>
#include <cuda_fp16.h>
#include <cstdint>

// Problem constants (fixed by the dataset)
#define NN 50000
#define EE 800000
#define IN_C 256
#define HID_C 128
#define OUT_C 64
#define NSCAN 49   // ceil(NN / 1024)

// ---------------------------------------------------------------------------
// Scratch (device globals). All vector-accessed buffers 16B-aligned.
// h1/h2 are fp16 (gather-bandwidth halving); t1 stays fp32 (gemm2 input).
// ---------------------------------------------------------------------------
__device__ int   g_deg[NN];
__device__ int   g_rowptr[NN + 1];
__device__ int   g_cursor[NN];
__device__ int   g_sagg[64];     // per-block scan aggregates
__device__ int   g_sflag[64];    // 0 = not published, 1 = aggregate ready
__device__ int   g_csr[EE];
__device__ __align__(16) __half g_h1[(size_t)NN * HID_C];
__device__ __align__(16) float  g_t1[(size_t)NN * HID_C];
__device__ __align__(16) __half g_h2[(size_t)NN * OUT_C];
// Weight images: W^T in bf16 hi/lo, row-major [n][k] (k contiguous)
__device__ __align__(16) __nv_bfloat16 g_Wt1h[HID_C * IN_C];
__device__ __align__(16) __nv_bfloat16 g_Wt1l[HID_C * IN_C];
__device__ __align__(16) __nv_bfloat16 g_Wt2h[OUT_C * HID_C];
__device__ __align__(16) __nv_bfloat16 g_Wt2l[OUT_C * HID_C];

// ---------------------------------------------------------------------------
// Side stream + events for fork-join overlap (created once at process init).
// ---------------------------------------------------------------------------
struct StreamBundle {
    cudaStream_t s1;
    cudaEvent_t  ev_start, ev_deg, ev_gemm1;
    StreamBundle() {
        cudaStreamCreateWithFlags(&s1, cudaStreamNonBlocking);
        cudaEventCreateWithFlags(&ev_start, cudaEventDisableTiming);
        cudaEventCreateWithFlags(&ev_deg,   cudaEventDisableTiming);
        cudaEventCreateWithFlags(&ev_gemm1, cudaEventDisableTiming);
    }
};
static StreamBundle g_sb;

// ---------------------------------------------------------------------------
// PTX helpers (arch-agnostic: ldmatrix sm_75+, mma bf16 sm_80+)
// ---------------------------------------------------------------------------
__device__ __forceinline__ uint32_t smem_u32(const void* p) {
    uint32_t a;
    asm("{ .reg .u64 t; cvta.to.shared.u64 t, %1; cvt.u32.u64 %0, t; }"
        : "=r"(a) : "l"(p));
    return a;
}
__device__ __forceinline__ void ldsm_x4(uint32_t* r, uint32_t addr) {
    asm volatile("ldmatrix.sync.aligned.m8n8.x4.shared.b16 {%0,%1,%2,%3}, [%4];"
                 : "=r"(r[0]), "=r"(r[1]), "=r"(r[2]), "=r"(r[3]) : "r"(addr));
}
__device__ __forceinline__ void mma_bf16(float* d, const uint32_t* a,
                                         const uint32_t* b) {
    asm volatile(
        "mma.sync.aligned.m16n8k16.row.col.f32.bf16.bf16.f32 "
        "{%0,%1,%2,%3}, {%4,%5,%6,%7}, {%8,%9}, {%0,%1,%2,%3};"
        : "+f"(d[0]), "+f"(d[1]), "+f"(d[2]), "+f"(d[3])
        : "r"(a[0]), "r"(a[1]), "r"(a[2]), "r"(a[3]), "r"(b[0]), "r"(b[1]));
}
__device__ __forceinline__ uint32_t pack2(__nv_bfloat16 lo, __nv_bfloat16 hi) {
    return ((uint32_t)__bfloat16_as_ushort(hi) << 16) | __bfloat16_as_ushort(lo);
}
__device__ __forceinline__ float dinv_of(int node) {
    return rsqrtf((float)(g_deg[node] + 1));   // +1 self-loop
}

// ---------------------------------------------------------------------------
// Degree / norm. edge_index is INT32 (JAX x64 disabled).
// ---------------------------------------------------------------------------
__global__ void k_clear_deg() {
    int i = blockIdx.x * blockDim.x + threadIdx.x;
    if (i < NN) g_deg[i] = 0;
    if (i < 64) g_sflag[i] = 0;      // reset scan flags for this replay
}
__global__ void k_count_deg(const int* __restrict__ dst) {
    int e = blockIdx.x * blockDim.x + threadIdx.x;
    if (e < EE) {
        unsigned d = (unsigned)dst[e];
        if (d < NN) atomicAdd(&g_deg[d], 1);
    }
}

// ---------------------------------------------------------------------------
// Single-pass exclusive scan of g_deg -> g_rowptr/g_cursor.
// ---------------------------------------------------------------------------
__global__ void k_scan() {
    __shared__ int sm[1024];
    __shared__ int spre[64];
    __shared__ int s_off;
    const int tid = threadIdx.x;
    const int bid = blockIdx.x;
    const int i = bid * 1024 + tid;

    int v = (i < NN) ? g_deg[i] : 0;
    sm[tid] = v;
    __syncthreads();
#pragma unroll
    for (int off = 1; off < 1024; off <<= 1) {
        int t = (tid >= off) ? sm[tid - off] : 0;
        __syncthreads();
        sm[tid] += t;
        __syncthreads();
    }
    int incl = sm[tid];

    if (tid == 1023) {
        g_sagg[bid] = incl;
        __threadfence();
        atomicExch(&g_sflag[bid], 1);
    }
    if (tid < 64) {
        int val = 0;
        if (tid < bid) {
            while (atomicAdd(&g_sflag[tid], 0) == 0) { }
            val = atomicAdd(&g_sagg[tid], 0);
        }
        spre[tid] = val;
    }
    __syncthreads();
    if (tid == 0) {
        int o = 0;
#pragma unroll
        for (int b = 0; b < 64; b++) o += spre[b];
        s_off = o;
    }
    __syncthreads();
    const int off = s_off;
    if (i < NN) {
        int r = incl - v + off;     // exclusive prefix
        g_rowptr[i] = r;
        g_cursor[i] = r;
    }
    if (i == 0) g_rowptr[NN] = EE;
}

__global__ void k_fill_csr(const int* __restrict__ src,
                           const int* __restrict__ dst) {
    int e = blockIdx.x * blockDim.x + threadIdx.x;
    if (e < EE) {
        unsigned d = (unsigned)dst[e];
        unsigned s = (unsigned)src[e];
        if (d < NN && s < NN) {
            int pos = atomicAdd(&g_cursor[d], 1);
            if ((unsigned)pos < EE) g_csr[pos] = (int)s;
        }
    }
}

// ---------------------------------------------------------------------------
// Weight split (merged W1+W2): W[K,N] fp32 -> hi/lo bf16, layout [n][k]
// ---------------------------------------------------------------------------
__global__ void k_conv(const float* __restrict__ W1, const float* __restrict__ W2) {
    int i = blockIdx.x * blockDim.x + threadIdx.x;
    constexpr int T1 = IN_C * HID_C;
    constexpr int T2 = HID_C * OUT_C;
    if (i < T1) {
        int k = i / HID_C, n = i % HID_C;
        float v = W1[i];
        __nv_bfloat16 h = __float2bfloat16(v);
        __nv_bfloat16 l = __float2bfloat16(v - __bfloat162float(h));
        g_Wt1h[(size_t)n * IN_C + k] = h;
        g_Wt1l[(size_t)n * IN_C + k] = l;
    } else if (i < T1 + T2) {
        int j = i - T1;
        int k = j / OUT_C, n = j % OUT_C;
        float v = W2[j];
        __nv_bfloat16 h = __float2bfloat16(v);
        __nv_bfloat16 l = __float2bfloat16(v - __bfloat162float(h));
        g_Wt2h[(size_t)n * HID_C + k] = h;
        g_Wt2l[(size_t)n * HID_C + k] = l;
    }
}

// ---------------------------------------------------------------------------
// bf16x3 HMMA GEMM with register-prefetch pipeline:
//   C[row,:] = fp16( (A[row,:] @ W) * rsqrt(deg[row]+1) )
// ---------------------------------------------------------------------------
template <int K, int N>
__device__ __forceinline__ void mma_gemm_core(
        const float* __restrict__ A,
        const __nv_bfloat16* __restrict__ Wth,
        const __nv_bfloat16* __restrict__ Wtl,
        __half* __restrict__ C) {
    constexpr int KC  = 32;
    constexpr int KCP = 40;
    constexpr int KCH = K / KC;
    constexpr int WU  = N / 64;
    __shared__ __align__(16) __nv_bfloat16 sAh[128 * KCP];
    __shared__ __align__(16) __nv_bfloat16 sAl[128 * KCP];
    __shared__ __align__(16) __nv_bfloat16 sWh[N * KCP];
    __shared__ __align__(16) __nv_bfloat16 sWl[N * KCP];

    const int tid  = threadIdx.x;
    const int lane = tid & 31;
    const int warp = tid >> 5;
    const int wrow = warp * 16;
    const int rowBase = blockIdx.x * 128;

    const uint32_t sAh_b = smem_u32(sAh), sAl_b = smem_u32(sAl);
    const uint32_t sWh_b = smem_u32(sWh), sWl_b = smem_u32(sWl);

    float acc[N / 8][4];
#pragma unroll
    for (int t = 0; t < N / 8; t++)
#pragma unroll
        for (int q = 0; q < 4; q++) acc[t][q] = 0.f;

    const int g  = lane >> 3;
    const int r8 = lane & 7;

    float4 pa[4];
    uint4  pwh[WU], pwl[WU];

    auto loadA = [&](int c) {
#pragma unroll
        for (int u = 0; u < 4; u++) {
            int i = tid + u * 256;
            int r = i >> 3, kq = i & 7;
            int grow = rowBase + r;
            pa[u] = make_float4(0.f, 0.f, 0.f, 0.f);
            if (grow < NN)
                pa[u] = *reinterpret_cast<const float4*>(
                            A + (size_t)grow * K + c * KC + kq * 4);
        }
    };
    auto loadW = [&](int c) {
#pragma unroll
        for (int u = 0; u < WU; u++) {
            int i = tid + u * 256;
            int n = i >> 2, q = i & 3;
            pwh[u] = *reinterpret_cast<const uint4*>(
                         Wth + (size_t)n * K + c * KC + q * 8);
            pwl[u] = *reinterpret_cast<const uint4*>(
                         Wtl + (size_t)n * K + c * KC + q * 8);
        }
    };
    auto storeAW = [&]() {
#pragma unroll
        for (int u = 0; u < 4; u++) {
            int i = tid + u * 256;
            int r = i >> 3, kq = i & 7;
            float4 v = pa[u];
            __nv_bfloat16 hx = __float2bfloat16(v.x), hy = __float2bfloat16(v.y);
            __nv_bfloat16 hz = __float2bfloat16(v.z), hw = __float2bfloat16(v.w);
            __nv_bfloat16 lx = __float2bfloat16(v.x - __bfloat162float(hx));
            __nv_bfloat16 ly = __float2bfloat16(v.y - __bfloat162float(hy));
            __nv_bfloat16 lz = __float2bfloat16(v.z - __bfloat162float(hz));
            __nv_bfloat16 lw = __float2bfloat16(v.w - __bfloat162float(hw));
            *reinterpret_cast<uint2*>(&sAh[r * KCP + kq * 4]) =
                make_uint2(pack2(hx, hy), pack2(hz, hw));
            *reinterpret_cast<uint2*>(&sAl[r * KCP + kq * 4]) =
                make_uint2(pack2(lx, ly), pack2(lz, lw));
        }
#pragma unroll
        for (int u = 0; u < WU; u++) {
            int i = tid + u * 256;
            int n = i >> 2, q = i & 3;
            *reinterpret_cast<uint4*>(&sWh[n * KCP + q * 8]) = pwh[u];
            *reinterpret_cast<uint4*>(&sWl[n * KCP + q * 8]) = pwl[u];
        }
    };

    loadA(0);
    loadW(0);

    for (int c = 0; c < KCH; c++) {
        if (c) __syncthreads();
        storeAW();
        __syncthreads();
        if (c + 1 < KCH) {
            loadA(c + 1);
            loadW(c + 1);
        }

#pragma unroll
        for (int ks = 0; ks < KC / 16; ks++) {
            int k0 = ks * 16;
            uint32_t ah[4], al[4];
            {
                int arow = wrow + r8 + ((g & 1) << 3);
                int acol = k0 + ((g >> 1) << 3);
                uint32_t off = (uint32_t)(arow * KCP + acol) * 2;
                ldsm_x4(ah, sAh_b + off);
                ldsm_x4(al, sAl_b + off);
            }
#pragma unroll
            for (int np = 0; np < N / 16; np++) {
                int nrow = np * 16 + r8 + ((g >> 1) << 3);
                int kcol = k0 + ((g & 1) << 3);
                uint32_t boff = (uint32_t)(nrow * KCP + kcol) * 2;
                uint32_t bh[4], bl[4];
                ldsm_x4(bh, sWh_b + boff);
                ldsm_x4(bl, sWl_b + boff);
                mma_bf16(acc[2 * np],     ah, bh);
                mma_bf16(acc[2 * np],     ah, bl);
                mma_bf16(acc[2 * np],     al, bh);
                mma_bf16(acc[2 * np + 1], ah, bh + 2);
                mma_bf16(acc[2 * np + 1], ah, bl + 2);
                mma_bf16(acc[2 * np + 1], al, bh + 2);
            }
        }
    }

    int r0 = rowBase + wrow + (lane >> 2);
    int r1 = r0 + 8;
    int cbase = (lane & 3) * 2;
    float s0 = (r0 < NN) ? dinv_of(r0) : 0.f;
    float s1 = (r1 < NN) ? dinv_of(r1) : 0.f;
#pragma unroll
    for (int t = 0; t < N / 8; t++) {
        int col = t * 8 + cbase;
        if (r0 < NN)
            *reinterpret_cast<__half2*>(C + (size_t)r0 * N + col) =
                __floats2half2_rn(acc[t][0] * s0, acc[t][1] * s0);
        if (r1 < NN)
            *reinterpret_cast<__half2*>(C + (size_t)r1 * N + col) =
                __floats2half2_rn(acc[t][2] * s1, acc[t][3] * s1);
    }
}

__global__ void __launch_bounds__(256)
k_gemm1(const float* __restrict__ x) {
    mma_gemm_core<IN_C, HID_C>(x, g_Wt1h, g_Wt1l, g_h1);
}
__global__ void __launch_bounds__(256)
k_gemm2() {
    mma_gemm_core<HID_C, OUT_C>(g_t1, g_Wt2h, g_Wt2l, g_h2);
}

// ---------------------------------------------------------------------------
// Aggregation over fp16 rows, fp32 accumulate:
//   out[i] = act( dinv[i] * (hs[i] + sum_{s in N(i)} hs[s]) + b )
//   G = C/8 threads per node; one uint4 (8 halves) per thread per row.
// ---------------------------------------------------------------------------
template <int C, bool RELU>
__device__ __forceinline__ void aggregate_half_core(
        const __half* __restrict__ hs, const float* __restrict__ bias,
        float* __restrict__ out) {
    constexpr int G   = C / 8;       // threads per node
    constexpr int NPB = 128 / G;     // nodes per 128-thread block
    const int local = threadIdx.x / G;
    const int lane  = threadIdx.x % G;
    const int node  = blockIdx.x * NPB + local;
    if (node >= NN) return;

    const uint4* base = reinterpret_cast<const uint4*>(hs);
    float acc[8];
    {
        uint4 v = base[(size_t)node * G + lane];    // self-loop term
        const __half2* hp = reinterpret_cast<const __half2*>(&v);
#pragma unroll
        for (int q = 0; q < 4; q++) {
            float2 f = __half22float2(hp[q]);
            acc[2 * q] = f.x;  acc[2 * q + 1] = f.y;
        }
    }
    const int beg = g_rowptr[node];
    const int end = g_rowptr[node + 1];
#pragma unroll 4
    for (int e = beg; e < end; e++) {
        int s = g_csr[e];
        uint4 v = base[(size_t)s * G + lane];
        const __half2* hp = reinterpret_cast<const __half2*>(&v);
#pragma unroll
        for (int q = 0; q < 4; q++) {
            float2 f = __half22float2(hp[q]);
            acc[2 * q] += f.x;  acc[2 * q + 1] += f.y;
        }
    }
    const float d = dinv_of(node);
    const float4* b4 = reinterpret_cast<const float4*>(bias);
    float4 ba = b4[lane * 2 + 0];
    float4 bb = b4[lane * 2 + 1];
    float4 o0 = make_float4(acc[0] * d + ba.x, acc[1] * d + ba.y,
                            acc[2] * d + ba.z, acc[3] * d + ba.w);
    float4 o1 = make_float4(acc[4] * d + bb.x, acc[5] * d + bb.y,
                            acc[6] * d + bb.z, acc[7] * d + bb.w);
    if (RELU) {
        o0.x = fmaxf(o0.x, 0.f); o0.y = fmaxf(o0.y, 0.f);
        o0.z = fmaxf(o0.z, 0.f); o0.w = fmaxf(o0.w, 0.f);
        o1.x = fmaxf(o1.x, 0.f); o1.y = fmaxf(o1.y, 0.f);
        o1.z = fmaxf(o1.z, 0.f); o1.w = fmaxf(o1.w, 0.f);
    }
    float4* o4 = reinterpret_cast<float4*>(out);
    o4[(size_t)node * (C / 4) + lane * 2 + 0] = o0;
    o4[(size_t)node * (C / 4) + lane * 2 + 1] = o1;
}

__global__ void __launch_bounds__(128)
k_agg1(const float* __restrict__ b1) {
    aggregate_half_core<HID_C, true>(g_h1, b1, g_t1);
}
__global__ void __launch_bounds__(128)
k_agg2(const float* __restrict__ b2, float* __restrict__ out) {
    aggregate_half_core<OUT_C, false>(g_h2, b2, out);
}

// ---------------------------------------------------------------------------
// Launch: fork-join across two streams (capture-legal event fork). 9 kernels.
//   s0: clear -> count -> [ev_deg] -> scan -> fill_csr
//       -> wait(ev_gemm1) -> agg1 -> gemm2 -> agg2
//   s1: wait(ev_start) -> conv -> wait(ev_deg) -> gemm1 -> [ev_gemm1]
// ---------------------------------------------------------------------------
extern "C" void kernel_launch(void* const* d_in, const int* in_sizes, int n_in,
                              void* d_out, int out_size) {
    const float* x   = (const float*)d_in[0];
    const int*   ei  = (const int*)d_in[1];     // int32 edge_index
    const float* W1  = (const float*)d_in[2];
    const float* b1  = (const float*)d_in[3];
    const float* W2  = (const float*)d_in[4];
    const float* b2  = (const float*)d_in[5];
    float*       out = (float*)d_out;

    const int* src = ei;
    const int* dst = ei + EE;

    const int TB = 256;
    const int nBlkN = (NN + TB - 1) / TB;
    const int nBlkE = (EE + TB - 1) / TB;
    const int nTiles = (NN + 127) / 128;   // 391

    cudaStream_t s0 = 0;            // harness-captured (legacy) stream
    cudaStream_t s1 = g_sb.s1;

    // fork s1 off the captured stream
    cudaEventRecord(g_sb.ev_start, s0);
    cudaStreamWaitEvent(s1, g_sb.ev_start, 0);

    // s1: weight images (no deps)
    {
        constexpr int TOT = IN_C * HID_C + HID_C * OUT_C;
        k_conv<<<(TOT + 255) / 256, 256, 0, s1>>>(W1, W2);
    }

    // s0: degree
    k_clear_deg<<<nBlkN, TB, 0, s0>>>();
    k_count_deg<<<nBlkE, TB, 0, s0>>>(dst);
    cudaEventRecord(g_sb.ev_deg, s0);

    // s0: single-pass scan + csr fill
    k_scan<<<NSCAN, 1024, 0, s0>>>();
    k_fill_csr<<<nBlkE, TB, 0, s0>>>(src, dst);

    // s1: gemm1 (needs x, W images, deg for epilogue dinv)
    cudaStreamWaitEvent(s1, g_sb.ev_deg, 0);
    k_gemm1<<<nTiles, 256, 0, s1>>>(x);
    cudaEventRecord(g_sb.ev_gemm1, s1);

    // join: agg1 needs csr (s0) + h1 (s1)
    cudaStreamWaitEvent(s0, g_sb.ev_gemm1, 0);
    {
        constexpr int NPB = 128 / (HID_C / 8);   // 8 nodes / block
        int grid = (NN + NPB - 1) / NPB;
        k_agg1<<<grid, 128, 0, s0>>>(b1);
    }
    k_gemm2<<<nTiles, 256, 0, s0>>>();
    {
        constexpr int NPB = 128 / (OUT_C / 8);   // 16 nodes / block
        int grid = (NN + NPB - 1) / NPB;
        k_agg2<<<grid, 128, 0, s0>>>(b2, out);
    }
}